// round 1
// baseline (speedup 1.0000x reference)
#include <cuda_runtime.h>
#include <cstdint>

// ---------------------------------------------------------------------------
// GraphSAGE 2-layer, N=100000 nodes, E=1600000 edges, 128 -> 128 -> 64.
//   layer1: h1 = relu( mean_agg(x) @ Wl1 + x @ Wr1 + b1 )
//   layer2: out = mean_agg(h1) @ Wl2 + h1 @ Wr2 + b2
//           restructured: p = h1@Wl2, q = h1@Wr2,  out = mean_agg(p) + q + b2
// Strategy: build CSR once (no float atomics), warp-per-node gathers (L2
// resident), tf32 mma.sync GEMMs.
// ---------------------------------------------------------------------------

#define NNODES_MAX 100000
#define EDGES_MAX  1600000
#define SCAN_BLK   1024

__device__ int   d_is64;
__device__ int   d_deg[NNODES_MAX + 1];
__device__ int   d_rowptr[NNODES_MAX + 1];
__device__ int   d_cur[NNODES_MAX + 1];
__device__ int   d_bsums[1024];
__device__ int   d_adj[EDGES_MAX];
__device__ float d_agg1[(size_t)NNODES_MAX * 128];
__device__ float d_h1[(size_t)NNODES_MAX * 128];
__device__ float d_pq[(size_t)NNODES_MAX * 128];

// ---------------------------------------------------------------------------
// Small utility kernels
// ---------------------------------------------------------------------------

__global__ void k_init(int n) {
    int i = blockIdx.x * blockDim.x + threadIdx.x;
    if (i < n) d_deg[i] = 0;
    if (i == 0) d_is64 = 1;
}

// If edge_index is int32, odd 32-bit words are random node ids (virtually
// never all zero). If int64 (values < 2^31), every odd word is 0.
__global__ void k_detect(const unsigned int* __restrict__ w, int nchk) {
    int i = blockIdx.x * blockDim.x + threadIdx.x;
    if (i < nchk && w[2 * i + 1] != 0) d_is64 = 0;
}

__global__ void k_hist(const void* __restrict__ ei, int E) {
    int e = blockIdx.x * blockDim.x + threadIdx.x;
    if (e >= E) return;
    int is64 = d_is64;
    int dst = is64 ? (int)((const long long*)ei)[(long long)E + e]
                   : ((const int*)ei)[E + e];
    atomicAdd(&d_deg[dst], 1);
}

__global__ void k_scan1(int n) {
    __shared__ int wsum[32];
    int i = blockIdx.x * SCAN_BLK + threadIdx.x;
    int v = (i < n) ? d_deg[i] : 0;
    int lane = threadIdx.x & 31, w = threadIdx.x >> 5;
    int inc = v;
#pragma unroll
    for (int o = 1; o < 32; o <<= 1) {
        int t = __shfl_up_sync(0xffffffffu, inc, o);
        if (lane >= o) inc += t;
    }
    if (lane == 31) wsum[w] = inc;
    __syncthreads();
    if (w == 0) {
        int s = wsum[lane];
        int si = s;
#pragma unroll
        for (int o = 1; o < 32; o <<= 1) {
            int t = __shfl_up_sync(0xffffffffu, si, o);
            if (lane >= o) si += t;
        }
        wsum[lane] = si - s;  // exclusive warp offsets
    }
    __syncthreads();
    int excl = inc - v + wsum[w];
    if (i < n) d_rowptr[i] = excl;
    if (threadIdx.x == SCAN_BLK - 1) d_bsums[blockIdx.x] = excl + v;
}

__global__ void k_scan2(int nb) {
    __shared__ int s[1024];
    int i = threadIdx.x;
    s[i] = (i < nb) ? d_bsums[i] : 0;
    __syncthreads();
    if (i == 0) {
        int acc = 0;
        for (int j = 0; j < nb; j++) { int t = s[j]; s[j] = acc; acc += t; }
    }
    __syncthreads();
    if (i < nb) d_bsums[i] = s[i];
}

__global__ void k_scan3(int n) {
    int i = blockIdx.x * SCAN_BLK + threadIdx.x;
    if (i < n) {
        int v = d_rowptr[i] + d_bsums[blockIdx.x];
        d_rowptr[i] = v;
        d_cur[i] = v;
    }
}

__global__ void k_scatter(const void* __restrict__ ei, int E) {
    int e = blockIdx.x * blockDim.x + threadIdx.x;
    if (e >= E) return;
    int is64 = d_is64;
    int src, dst;
    if (is64) {
        const long long* p = (const long long*)ei;
        src = (int)p[e];
        dst = (int)p[(long long)E + e];
    } else {
        const int* p = (const int*)ei;
        src = p[e];
        dst = p[E + e];
    }
    int pos = atomicAdd(&d_cur[dst], 1);
    d_adj[pos] = src;
}

// ---------------------------------------------------------------------------
// Aggregation: warp per node, mean of neighbor rows (128 floats -> float4/lane)
// ---------------------------------------------------------------------------

__global__ void k_agg128(const float* __restrict__ feat, int n) {
    int gw = (blockIdx.x * blockDim.x + threadIdx.x) >> 5;
    if (gw >= n) return;
    int lane = threadIdx.x & 31;
    int start = d_rowptr[gw], deg = d_deg[gw];
    const float4* base = (const float4*)feat;
    float ax = 0.f, ay = 0.f, az = 0.f, aw = 0.f;
    int j = 0;
    for (; j + 4 <= deg; j += 4) {
        int n0 = d_adj[start + j + 0];
        int n1 = d_adj[start + j + 1];
        int n2 = d_adj[start + j + 2];
        int n3 = d_adj[start + j + 3];
        float4 v0 = __ldg(base + (size_t)n0 * 32 + lane);
        float4 v1 = __ldg(base + (size_t)n1 * 32 + lane);
        float4 v2 = __ldg(base + (size_t)n2 * 32 + lane);
        float4 v3 = __ldg(base + (size_t)n3 * 32 + lane);
        ax += v0.x + v1.x + v2.x + v3.x;
        ay += v0.y + v1.y + v2.y + v3.y;
        az += v0.z + v1.z + v2.z + v3.z;
        aw += v0.w + v1.w + v2.w + v3.w;
    }
    for (; j < deg; j++) {
        int nb = d_adj[start + j];
        float4 v = __ldg(base + (size_t)nb * 32 + lane);
        ax += v.x; ay += v.y; az += v.z; aw += v.w;
    }
    float inv = 1.0f / (float)(deg > 0 ? deg : 1);
    float4 r = make_float4(ax * inv, ay * inv, az * inv, aw * inv);
    ((float4*)d_agg1)[(size_t)gw * 32 + lane] = r;
}

// Final: out = mean_agg(p) + q + b2  where pq = [p (64) | q (64)] per row.
__global__ void k_final(float* __restrict__ out, const float* __restrict__ b2, int n) {
    int gw = (blockIdx.x * blockDim.x + threadIdx.x) >> 5;
    if (gw >= n) return;
    int lane = threadIdx.x & 31;
    int start = d_rowptr[gw], deg = d_deg[gw];
    const float* pq = d_pq;
    float ax = 0.f, ay = 0.f;
    int j = 0;
    for (; j + 4 <= deg; j += 4) {
        int n0 = d_adj[start + j + 0];
        int n1 = d_adj[start + j + 1];
        int n2 = d_adj[start + j + 2];
        int n3 = d_adj[start + j + 3];
        float2 v0 = __ldg((const float2*)(pq + (size_t)n0 * 128) + lane);
        float2 v1 = __ldg((const float2*)(pq + (size_t)n1 * 128) + lane);
        float2 v2 = __ldg((const float2*)(pq + (size_t)n2 * 128) + lane);
        float2 v3 = __ldg((const float2*)(pq + (size_t)n3 * 128) + lane);
        ax += v0.x + v1.x + v2.x + v3.x;
        ay += v0.y + v1.y + v2.y + v3.y;
    }
    for (; j < deg; j++) {
        int nb = d_adj[start + j];
        float2 v = __ldg((const float2*)(pq + (size_t)nb * 128) + lane);
        ax += v.x; ay += v.y;
    }
    float inv = 1.0f / (float)(deg > 0 ? deg : 1);
    float2 q = *(const float2*)(pq + (size_t)gw * 128 + 64 + 2 * lane);
    float2 bb = *(const float2*)(b2 + 2 * lane);
    float2 r;
    r.x = ax * inv + q.x + bb.x;
    r.y = ay * inv + q.y + bb.y;
    *(float2*)(out + (size_t)gw * 64 + 2 * lane) = r;
}

// ---------------------------------------------------------------------------
// tf32 mma.sync GEMM.
//  mode 1: h1 = relu([agg1 | x](K=256) @ [Wl1 ; Wr1] + b1), N=128
//  mode 2: pq = h1(K=128) @ [Wl2 | Wr2], N=128 (first 64 cols Wl2, last Wr2)
// BM=128, BN=128, BK=32, 256 threads, warp tile 32x64.
// ---------------------------------------------------------------------------

__device__ __forceinline__ uint32_t f2tf32(float f) {
    uint32_t u;
    asm("cvt.rna.tf32.f32 %0, %1;" : "=r"(u) : "f"(f));
    return u;
}

__device__ __forceinline__ void mma_tf32(float c[4],
                                         uint32_t a0, uint32_t a1, uint32_t a2, uint32_t a3,
                                         uint32_t b0, uint32_t b1) {
    asm volatile(
        "mma.sync.aligned.m16n8k8.row.col.f32.tf32.tf32.f32 "
        "{%0,%1,%2,%3},{%4,%5,%6,%7},{%8,%9},{%0,%1,%2,%3};"
        : "+f"(c[0]), "+f"(c[1]), "+f"(c[2]), "+f"(c[3])
        : "r"(a0), "r"(a1), "r"(a2), "r"(a3), "r"(b0), "r"(b1));
}

__global__ __launch_bounds__(256) void k_gemm(
    const float* __restrict__ A0, const float* __restrict__ A1,
    const float* __restrict__ W0, const float* __restrict__ W1,
    const float* __restrict__ bias, float* __restrict__ out,
    int M, int mode) {
    __shared__ __align__(16) uint32_t As[128][36];
    __shared__ __align__(16) uint32_t Bs[32][132];

    const int tid = threadIdx.x;
    const int lane = tid & 31;
    const int warp = tid >> 5;
    const int wm = warp >> 1;      // 0..3 -> 32-row band
    const int wn = warp & 1;       // 0..1 -> 64-col band
    const int g = lane >> 2;       // group id (row within mma tile)
    const int t = lane & 3;        // thread-in-group (k / col pair index)
    const int row0 = blockIdx.x * 128;
    const int K = (mode == 1) ? 256 : 128;
    const int ktiles = K / 32;

    float acc[2][8][4];
#pragma unroll
    for (int mi = 0; mi < 2; mi++)
#pragma unroll
        for (int ni = 0; ni < 8; ni++)
#pragma unroll
            for (int r = 0; r < 4; r++) acc[mi][ni][r] = 0.f;

    for (int kt = 0; kt < ktiles; kt++) {
        // --- load A tile (128 x 32) ---
#pragma unroll
        for (int v = 0; v < 4; v++) {
            int idx = v * 256 + tid;
            int r = idx >> 3;       // 0..127
            int c4 = idx & 7;       // 0..7 (float4 slot)
            int grow = row0 + r;
            int gk = kt * 32 + c4 * 4;
            float4 a = make_float4(0.f, 0.f, 0.f, 0.f);
            if (grow < M) {
                const float* src;
                if (mode == 1)
                    src = (gk < 128) ? (A0 + (size_t)grow * 128 + gk)
                                     : (A1 + (size_t)grow * 128 + gk - 128);
                else
                    src = A0 + (size_t)grow * 128 + gk;
                a = *(const float4*)src;
            }
            uint32_t* d = &As[r][c4 * 4];
            d[0] = f2tf32(a.x); d[1] = f2tf32(a.y);
            d[2] = f2tf32(a.z); d[3] = f2tf32(a.w);
        }
        // --- load W tile (32 x 128) ---
#pragma unroll
        for (int v = 0; v < 4; v++) {
            int idx = v * 256 + tid;
            int r = idx >> 5;       // 0..31 (k within tile)
            int c4 = idx & 31;      // 0..31
            int gk = kt * 32 + r;
            int col = c4 * 4;
            const float* src;
            if (mode == 1)
                src = (gk < 128) ? (W0 + (size_t)gk * 128 + col)
                                 : (W1 + (size_t)(gk - 128) * 128 + col);
            else
                src = (col < 64) ? (W0 + (size_t)gk * 64 + col)
                                 : (W1 + (size_t)gk * 64 + col - 64);
            float4 w = *(const float4*)src;
            uint32_t* d = &Bs[r][col];
            d[0] = f2tf32(w.x); d[1] = f2tf32(w.y);
            d[2] = f2tf32(w.z); d[3] = f2tf32(w.w);
        }
        __syncthreads();

#pragma unroll
        for (int ks = 0; ks < 4; ks++) {
            int kb = ks * 8;
            uint32_t af[2][4];
#pragma unroll
            for (int mi = 0; mi < 2; mi++) {
                int rb = wm * 32 + mi * 16;
                af[mi][0] = As[rb + g][kb + t];
                af[mi][1] = As[rb + g + 8][kb + t];
                af[mi][2] = As[rb + g][kb + t + 4];
                af[mi][3] = As[rb + g + 8][kb + t + 4];
            }
#pragma unroll
            for (int ni = 0; ni < 8; ni++) {
                int cn = wn * 64 + ni * 8 + g;
                uint32_t b0 = Bs[kb + t][cn];
                uint32_t b1 = Bs[kb + t + 4][cn];
                mma_tf32(acc[0][ni], af[0][0], af[0][1], af[0][2], af[0][3], b0, b1);
                mma_tf32(acc[1][ni], af[1][0], af[1][1], af[1][2], af[1][3], b0, b1);
            }
        }
        __syncthreads();
    }

    // --- epilogue ---
#pragma unroll
    for (int mi = 0; mi < 2; mi++) {
#pragma unroll
        for (int ni = 0; ni < 8; ni++) {
            int r0 = row0 + wm * 32 + mi * 16 + g;
            int cc = wn * 64 + ni * 8 + 2 * t;
            float v00 = acc[mi][ni][0], v01 = acc[mi][ni][1];
            float v10 = acc[mi][ni][2], v11 = acc[mi][ni][3];
            if (mode == 1) {
                float bb0 = bias[cc], bb1 = bias[cc + 1];
                v00 = fmaxf(v00 + bb0, 0.f);
                v01 = fmaxf(v01 + bb1, 0.f);
                v10 = fmaxf(v10 + bb0, 0.f);
                v11 = fmaxf(v11 + bb1, 0.f);
            }
            if (r0 < M) {
                float2 s0 = make_float2(v00, v01);
                *(float2*)(out + (size_t)r0 * 128 + cc) = s0;
            }
            if (r0 + 8 < M) {
                float2 s1 = make_float2(v10, v11);
                *(float2*)(out + (size_t)(r0 + 8) * 128 + cc) = s1;
            }
        }
    }
}

// ---------------------------------------------------------------------------
// Launch
// ---------------------------------------------------------------------------

extern "C" void kernel_launch(void* const* d_in, const int* in_sizes, int n_in,
                              void* d_out, int out_size) {
    const float* x   = (const float*)d_in[0];
    const void*  ei  = d_in[1];
    const float* Wl1 = (const float*)d_in[2];
    const float* Wr1 = (const float*)d_in[3];
    const float* b1  = (const float*)d_in[4];
    const float* Wl2 = (const float*)d_in[5];
    const float* Wr2 = (const float*)d_in[6];
    const float* b2  = (const float*)d_in[7];
    float* out = (float*)d_out;

    int n = in_sizes[0] / 128;          // 100000
    int E = in_sizes[1] / 2;            // 1600000

    // pointers to device globals (device code references them directly)
    float* agg1; cudaGetSymbolAddress((void**)&agg1, d_agg1);
    float* h1;   cudaGetSymbolAddress((void**)&h1, d_h1);
    float* pq;   cudaGetSymbolAddress((void**)&pq, d_pq);

    int nb = (n + SCAN_BLK - 1) / SCAN_BLK;

    k_init<<<(n + 255) / 256, 256>>>(n);
    k_detect<<<16, 256>>>((const unsigned int*)ei, 4096);
    k_hist<<<(E + 255) / 256, 256>>>(ei, E);
    k_scan1<<<nb, SCAN_BLK>>>(n);
    k_scan2<<<1, 1024>>>(nb);
    k_scan3<<<nb, SCAN_BLK>>>(n);
    k_scatter<<<(E + 255) / 256, 256>>>(ei, E);

    // layer 1
    k_agg128<<<(n * 32 + 255) / 256, 256>>>(x, n);
    k_gemm<<<(n + 127) / 128, 256>>>(agg1, x, Wl1, Wr1, b1, h1, n, 1);

    // layer 2 (GEMM first, then 64-dim aggregation fused with residual+bias)
    k_gemm<<<(n + 127) / 128, 256>>>(h1, nullptr, Wl2, Wr2, nullptr, pq, n, 2);
    k_final<<<(n * 32 + 255) / 256, 256>>>(out, b2, n);
}

// round 2
// speedup vs baseline: 1.3867x; 1.3867x over previous
#include <cuda_runtime.h>
#include <cstdint>

// ---------------------------------------------------------------------------
// GraphSAGE 2-layer, N=100000, E=1600000, 128 -> 128 -> 64.
//   layer1: h1 = relu( mean_agg(x) @ Wl1 + x @ Wr1 + b1 )
//   layer2: out = mean_agg(h1 @ Wl2) + h1 @ Wr2 + b2   (agg is linear)
// CSR build (no float atomics) -> warp-gather mean agg -> fused tf32 mma GEMM
// (layer1 GEMM K=256 + layer2 GEMM K=128 in one kernel, h1 never leaves smem)
// -> final 64-dim gather + residual + bias.
// ---------------------------------------------------------------------------

#define NNODES_MAX 100000
#define EDGES_MAX  1600000
#define SCAN_BLK   1024

__device__ int   d_is64;
__device__ int   d_deg[NNODES_MAX + 1];
__device__ int   d_rowptr[NNODES_MAX + 1];
__device__ int   d_cur[NNODES_MAX + 1];
__device__ int   d_bsums[1024];
__device__ int   d_adj[EDGES_MAX];
__device__ float d_agg1[(size_t)NNODES_MAX * 128];
__device__ float d_pq[(size_t)NNODES_MAX * 128];

// ---------------------------------------------------------------------------
// CSR build
// ---------------------------------------------------------------------------

// int32 edge arrays have random nonzero odd words; int64 (<2^31) has all-zero.
__global__ void k_detect(const unsigned int* __restrict__ w, int nchk) {
    int i = blockIdx.x * blockDim.x + threadIdx.x;
    if (i < nchk && w[2 * i + 1] != 0) d_is64 = 0;
}

__global__ void k_hist(const void* __restrict__ ei, int E) {
    int e = blockIdx.x * blockDim.x + threadIdx.x;
    if (e >= E) return;
    int dst = d_is64 ? (int)((const long long*)ei)[(long long)E + e]
                     : ((const int*)ei)[E + e];
    atomicAdd(&d_deg[dst], 1);
}

__global__ void k_scan1(int n) {
    __shared__ int wsum[32];
    int i = blockIdx.x * SCAN_BLK + threadIdx.x;
    int v = (i < n) ? d_deg[i] : 0;
    int lane = threadIdx.x & 31, w = threadIdx.x >> 5;
    int inc = v;
#pragma unroll
    for (int o = 1; o < 32; o <<= 1) {
        int t = __shfl_up_sync(0xffffffffu, inc, o);
        if (lane >= o) inc += t;
    }
    if (lane == 31) wsum[w] = inc;
    __syncthreads();
    if (w == 0) {
        int s = wsum[lane];
        int si = s;
#pragma unroll
        for (int o = 1; o < 32; o <<= 1) {
            int t = __shfl_up_sync(0xffffffffu, si, o);
            if (lane >= o) si += t;
        }
        wsum[lane] = si - s;
    }
    __syncthreads();
    int excl = inc - v + wsum[w];
    if (i < n) d_rowptr[i] = excl;
    if (threadIdx.x == SCAN_BLK - 1) d_bsums[blockIdx.x] = excl + v;
}

__global__ void k_scan2(int nb) {
    __shared__ int s[1024];
    int i = threadIdx.x;
    s[i] = (i < nb) ? d_bsums[i] : 0;
    __syncthreads();
    if (i == 0) {
        int acc = 0;
        for (int j = 0; j < nb; j++) { int t = s[j]; s[j] = acc; acc += t; }
    }
    __syncthreads();
    if (i < nb) d_bsums[i] = s[i];
}

__global__ void k_scan3(int n) {
    int i = blockIdx.x * SCAN_BLK + threadIdx.x;
    if (i < n) {
        int v = d_rowptr[i] + d_bsums[blockIdx.x];
        d_rowptr[i] = v;
        d_cur[i] = v;
    }
}

__global__ void k_scatter(const void* __restrict__ ei, int E) {
    int e = blockIdx.x * blockDim.x + threadIdx.x;
    if (e >= E) return;
    int src, dst;
    if (d_is64) {
        const long long* p = (const long long*)ei;
        src = (int)p[e];
        dst = (int)p[(long long)E + e];
    } else {
        const int* p = (const int*)ei;
        src = p[e];
        dst = p[E + e];
    }
    int pos = atomicAdd(&d_cur[dst], 1);
    d_adj[pos] = src;
}

// ---------------------------------------------------------------------------
// Aggregation (warp per node)
// ---------------------------------------------------------------------------

__global__ void k_agg128(const float* __restrict__ feat, int n) {
    int gw = (blockIdx.x * blockDim.x + threadIdx.x) >> 5;
    if (gw >= n) return;
    int lane = threadIdx.x & 31;
    int start = d_rowptr[gw], deg = d_deg[gw];
    const float4* base = (const float4*)feat;
    float ax = 0.f, ay = 0.f, az = 0.f, aw = 0.f;
    int j = 0;
    for (; j + 4 <= deg; j += 4) {
        int n0 = d_adj[start + j + 0];
        int n1 = d_adj[start + j + 1];
        int n2 = d_adj[start + j + 2];
        int n3 = d_adj[start + j + 3];
        float4 v0 = __ldg(base + (size_t)n0 * 32 + lane);
        float4 v1 = __ldg(base + (size_t)n1 * 32 + lane);
        float4 v2 = __ldg(base + (size_t)n2 * 32 + lane);
        float4 v3 = __ldg(base + (size_t)n3 * 32 + lane);
        ax += v0.x + v1.x + v2.x + v3.x;
        ay += v0.y + v1.y + v2.y + v3.y;
        az += v0.z + v1.z + v2.z + v3.z;
        aw += v0.w + v1.w + v2.w + v3.w;
    }
    for (; j < deg; j++) {
        int nb = d_adj[start + j];
        float4 v = __ldg(base + (size_t)nb * 32 + lane);
        ax += v.x; ay += v.y; az += v.z; aw += v.w;
    }
    float inv = 1.0f / (float)(deg > 0 ? deg : 1);
    ((float4*)d_agg1)[(size_t)gw * 32 + lane] =
        make_float4(ax * inv, ay * inv, az * inv, aw * inv);
}

// out = mean_agg(p) + q + b2  with pq = [p(64) | q(64)] per row.
__global__ void k_final(float* __restrict__ out, const float* __restrict__ b2, int n) {
    int gw = (blockIdx.x * blockDim.x + threadIdx.x) >> 5;
    if (gw >= n) return;
    int lane = threadIdx.x & 31;
    int start = d_rowptr[gw], deg = d_deg[gw];
    const float* pq = d_pq;
    float ax = 0.f, ay = 0.f;
    int j = 0;
    for (; j + 4 <= deg; j += 4) {
        int n0 = d_adj[start + j + 0];
        int n1 = d_adj[start + j + 1];
        int n2 = d_adj[start + j + 2];
        int n3 = d_adj[start + j + 3];
        float2 v0 = __ldg((const float2*)(pq + (size_t)n0 * 128) + lane);
        float2 v1 = __ldg((const float2*)(pq + (size_t)n1 * 128) + lane);
        float2 v2 = __ldg((const float2*)(pq + (size_t)n2 * 128) + lane);
        float2 v3 = __ldg((const float2*)(pq + (size_t)n3 * 128) + lane);
        ax += v0.x + v1.x + v2.x + v3.x;
        ay += v0.y + v1.y + v2.y + v3.y;
    }
    for (; j < deg; j++) {
        int nb = d_adj[start + j];
        float2 v = __ldg((const float2*)(pq + (size_t)nb * 128) + lane);
        ax += v.x; ay += v.y;
    }
    float inv = 1.0f / (float)(deg > 0 ? deg : 1);
    float2 q = *(const float2*)(pq + (size_t)gw * 128 + 64 + 2 * lane);
    float2 bb = *(const float2*)(b2 + 2 * lane);
    float2 r;
    r.x = ax * inv + q.x + bb.x;
    r.y = ay * inv + q.y + bb.y;
    *(float2*)(out + (size_t)gw * 64 + 2 * lane) = r;
}

// ---------------------------------------------------------------------------
// Fused tf32 GEMM:
//  phase1: acc = [agg1 | x](K=256) @ [Wl1;Wr1](256x128); h1 = relu(acc + b1)
//          -> tf32 into smem (As2)
//  phase2: pq = h1(K=128) @ [Wl2 | Wr2](128x128)  (cols 0..63 = p, 64..127 = q)
// BM=128, BN=128, BK=32, 256 threads, warp tile 32x64.
// Bs stride 136 words -> bank = 8t+g, conflict-free fragment loads.
// LDG for next tile issued right after STS (regs free) -> hides L2 latency
// behind the mma phase.
// ---------------------------------------------------------------------------

#define BS_STRIDE 136
#define AS_STRIDE 36
#define AS2_STRIDE 132
#define SMEM_WORDS (32 * BS_STRIDE + 128 * AS2_STRIDE)
#define SMEM_BYTES (SMEM_WORDS * 4)

__device__ __forceinline__ uint32_t f2tf32(float f) {
    uint32_t u;
    asm("cvt.rna.tf32.f32 %0, %1;" : "=r"(u) : "f"(f));
    return u;
}

__device__ __forceinline__ void mma_tf32(float c[4],
                                         uint32_t a0, uint32_t a1, uint32_t a2, uint32_t a3,
                                         uint32_t b0, uint32_t b1) {
    asm volatile(
        "mma.sync.aligned.m16n8k8.row.col.f32.tf32.tf32.f32 "
        "{%0,%1,%2,%3},{%4,%5,%6,%7},{%8,%9},{%0,%1,%2,%3};"
        : "+f"(c[0]), "+f"(c[1]), "+f"(c[2]), "+f"(c[3])
        : "r"(a0), "r"(a1), "r"(a2), "r"(a3), "r"(b0), "r"(b1));
}

__global__ __launch_bounds__(256, 2) void k_fused(
    const float* __restrict__ A0, const float* __restrict__ A1,
    const float* __restrict__ W1l, const float* __restrict__ W1r,
    const float* __restrict__ b1,
    const float* __restrict__ W2l, const float* __restrict__ W2r,
    float* __restrict__ pq, int M) {
    extern __shared__ uint32_t smem[];
    uint32_t (*Bs)[BS_STRIDE] = (uint32_t(*)[BS_STRIDE])smem;
    uint32_t (*As)[AS_STRIDE] = (uint32_t(*)[AS_STRIDE])(smem + 32 * BS_STRIDE);
    uint32_t (*As2)[AS2_STRIDE] = (uint32_t(*)[AS2_STRIDE])(smem + 32 * BS_STRIDE);

    const int tid = threadIdx.x;
    const int lane = tid & 31;
    const int warp = tid >> 5;
    const int wm = warp >> 1;      // 0..3 -> 32-row band
    const int wn = warp & 1;       // 0..1 -> 64-col band
    const int g = lane >> 2;
    const int t = lane & 3;
    const int row0 = blockIdx.x * 128;

    // per-thread tile-load coordinates
    const int la_r[4]  = {(0 * 256 + tid) >> 3, (1 * 256 + tid) >> 3,
                          (2 * 256 + tid) >> 3, (3 * 256 + tid) >> 3};
    const int la_c[4]  = {(tid & 7) * 4, (tid & 7) * 4, (tid & 7) * 4, (tid & 7) * 4};
    const int lb_r[4]  = {(0 * 256 + tid) >> 5, (1 * 256 + tid) >> 5,
                          (2 * 256 + tid) >> 5, (3 * 256 + tid) >> 5};
    const int lb_c    = (tid & 31) * 4;

    float acc[2][8][4];
#pragma unroll
    for (int mi = 0; mi < 2; mi++)
#pragma unroll
        for (int ni = 0; ni < 8; ni++)
#pragma unroll
            for (int r = 0; r < 4; r++) acc[mi][ni][r] = 0.f;

    float4 rA[4], rB[4];

    // --- initial loads, ktile 0 (phase 1: K = 256, tiles of 32) ---
#pragma unroll
    for (int v = 0; v < 4; v++) {
        int grow = row0 + la_r[v];
        int gk = la_c[v];               // kt=0
        rA[v] = make_float4(0.f, 0.f, 0.f, 0.f);
        if (grow < M) rA[v] = *(const float4*)(A0 + (size_t)grow * 128 + gk);
        rB[v] = *(const float4*)(W1l + (size_t)lb_r[v] * 128 + lb_c);
    }

    for (int kt = 0; kt < 8; kt++) {
        // store current tile to smem (tf32)
#pragma unroll
        for (int v = 0; v < 4; v++) {
            uint32_t* d = &As[la_r[v]][la_c[v]];
            d[0] = f2tf32(rA[v].x); d[1] = f2tf32(rA[v].y);
            d[2] = f2tf32(rA[v].z); d[3] = f2tf32(rA[v].w);
            uint32_t* e = &Bs[lb_r[v]][lb_c];
            e[0] = f2tf32(rB[v].x); e[1] = f2tf32(rB[v].y);
            e[2] = f2tf32(rB[v].z); e[3] = f2tf32(rB[v].w);
        }
        // prefetch next tile (overlaps with compute below)
        if (kt < 7) {
            int kt1 = kt + 1;
#pragma unroll
            for (int v = 0; v < 4; v++) {
                int grow = row0 + la_r[v];
                int gk = kt1 * 32 + la_c[v];
                rA[v] = make_float4(0.f, 0.f, 0.f, 0.f);
                if (grow < M) {
                    const float* src = (gk < 128)
                        ? (A0 + (size_t)grow * 128 + gk)
                        : (A1 + (size_t)grow * 128 + (gk - 128));
                    rA[v] = *(const float4*)src;
                }
                int wk = kt1 * 32 + lb_r[v];
                const float* wsrc = (wk < 128)
                    ? (W1l + (size_t)wk * 128 + lb_c)
                    : (W1r + (size_t)(wk - 128) * 128 + lb_c);
                rB[v] = *(const float4*)wsrc;
            }
        }
        __syncthreads();
#pragma unroll
        for (int ks = 0; ks < 4; ks++) {
            int kb = ks * 8;
            uint32_t af[2][4];
#pragma unroll
            for (int mi = 0; mi < 2; mi++) {
                int rb = wm * 32 + mi * 16;
                af[mi][0] = As[rb + g][kb + t];
                af[mi][1] = As[rb + g + 8][kb + t];
                af[mi][2] = As[rb + g][kb + t + 4];
                af[mi][3] = As[rb + g + 8][kb + t + 4];
            }
#pragma unroll
            for (int ni = 0; ni < 8; ni++) {
                int cn = wn * 64 + ni * 8 + g;
                uint32_t b0 = Bs[kb + t][cn];
                uint32_t b1v = Bs[kb + t + 4][cn];
                mma_tf32(acc[0][ni], af[0][0], af[0][1], af[0][2], af[0][3], b0, b1v);
                mma_tf32(acc[1][ni], af[1][0], af[1][1], af[1][2], af[1][3], b0, b1v);
            }
        }
        __syncthreads();
    }

    // --- phase-1 epilogue: h1 = relu(acc + b1) -> tf32 smem (As2, overlaps As) ---
    // prefetch W2 ktile 0 first so the LDG overlaps the STS work
#pragma unroll
    for (int v = 0; v < 4; v++) {
        int wk = lb_r[v];
        const float* wsrc = (lb_c < 64) ? (W2l + (size_t)wk * 64 + lb_c)
                                        : (W2r + (size_t)wk * 64 + (lb_c - 64));
        rB[v] = *(const float4*)wsrc;
    }
#pragma unroll
    for (int mi = 0; mi < 2; mi++) {
#pragma unroll
        for (int ni = 0; ni < 8; ni++) {
            int rr = wm * 32 + mi * 16 + g;
            int cc = wn * 64 + ni * 8 + 2 * t;
            float bb0 = b1[cc], bb1 = b1[cc + 1];
            As2[rr][cc]         = f2tf32(fmaxf(acc[mi][ni][0] + bb0, 0.f));
            As2[rr][cc + 1]     = f2tf32(fmaxf(acc[mi][ni][1] + bb1, 0.f));
            As2[rr + 8][cc]     = f2tf32(fmaxf(acc[mi][ni][2] + bb0, 0.f));
            As2[rr + 8][cc + 1] = f2tf32(fmaxf(acc[mi][ni][3] + bb1, 0.f));
        }
    }
#pragma unroll
    for (int mi = 0; mi < 2; mi++)
#pragma unroll
        for (int ni = 0; ni < 8; ni++)
#pragma unroll
            for (int r = 0; r < 4; r++) acc[mi][ni][r] = 0.f;

    // --- phase 2: pq = h1 @ [W2l | W2r], K = 128, 4 ktiles ---
    for (int kt = 0; kt < 4; kt++) {
#pragma unroll
        for (int v = 0; v < 4; v++) {
            uint32_t* e = &Bs[lb_r[v]][lb_c];
            e[0] = f2tf32(rB[v].x); e[1] = f2tf32(rB[v].y);
            e[2] = f2tf32(rB[v].z); e[3] = f2tf32(rB[v].w);
        }
        if (kt < 3) {
            int wk1 = (kt + 1) * 32;
#pragma unroll
            for (int v = 0; v < 4; v++) {
                int wk = wk1 + lb_r[v];
                const float* wsrc = (lb_c < 64)
                    ? (W2l + (size_t)wk * 64 + lb_c)
                    : (W2r + (size_t)wk * 64 + (lb_c - 64));
                rB[v] = *(const float4*)wsrc;
            }
        }
        __syncthreads();
        int kofs = kt * 32;
#pragma unroll
        for (int ks = 0; ks < 4; ks++) {
            int kb = ks * 8;
            uint32_t af[2][4];
#pragma unroll
            for (int mi = 0; mi < 2; mi++) {
                int rb = wm * 32 + mi * 16;
                af[mi][0] = As2[rb + g][kofs + kb + t];
                af[mi][1] = As2[rb + g + 8][kofs + kb + t];
                af[mi][2] = As2[rb + g][kofs + kb + t + 4];
                af[mi][3] = As2[rb + g + 8][kofs + kb + t + 4];
            }
#pragma unroll
            for (int ni = 0; ni < 8; ni++) {
                int cn = wn * 64 + ni * 8 + g;
                uint32_t b0 = Bs[kb + t][cn];
                uint32_t b1v = Bs[kb + t + 4][cn];
                mma_tf32(acc[0][ni], af[0][0], af[0][1], af[0][2], af[0][3], b0, b1v);
                mma_tf32(acc[1][ni], af[1][0], af[1][1], af[1][2], af[1][3], b0, b1v);
            }
        }
        __syncthreads();
    }

    // --- phase-2 epilogue: write pq ---
#pragma unroll
    for (int mi = 0; mi < 2; mi++) {
#pragma unroll
        for (int ni = 0; ni < 8; ni++) {
            int r0 = row0 + wm * 32 + mi * 16 + g;
            int cc = wn * 64 + ni * 8 + 2 * t;
            if (r0 < M)
                *(float2*)(pq + (size_t)r0 * 128 + cc) =
                    make_float2(acc[mi][ni][0], acc[mi][ni][1]);
            if (r0 + 8 < M)
                *(float2*)(pq + (size_t)(r0 + 8) * 128 + cc) =
                    make_float2(acc[mi][ni][2], acc[mi][ni][3]);
        }
    }
}

// ---------------------------------------------------------------------------
// Launch
// ---------------------------------------------------------------------------

extern "C" void kernel_launch(void* const* d_in, const int* in_sizes, int n_in,
                              void* d_out, int out_size) {
    const float* x   = (const float*)d_in[0];
    const void*  ei  = d_in[1];
    const float* Wl1 = (const float*)d_in[2];
    const float* Wr1 = (const float*)d_in[3];
    const float* b1  = (const float*)d_in[4];
    const float* Wl2 = (const float*)d_in[5];
    const float* Wr2 = (const float*)d_in[6];
    const float* b2  = (const float*)d_in[7];
    float* out = (float*)d_out;

    int n = in_sizes[0] / 128;
    int E = in_sizes[1] / 2;

    float* agg1; cudaGetSymbolAddress((void**)&agg1, d_agg1);
    float* pq;   cudaGetSymbolAddress((void**)&pq, d_pq);
    void* degp;  cudaGetSymbolAddress(&degp, d_deg);
    void* is64p; cudaGetSymbolAddress(&is64p, d_is64);

    static int smem_set = 0;
    if (!smem_set) {
        cudaFuncSetAttribute(k_fused, cudaFuncAttributeMaxDynamicSharedMemorySize,
                             SMEM_BYTES);
        smem_set = 1;
    }

    int nb = (n + SCAN_BLK - 1) / SCAN_BLK;

    cudaMemsetAsync(degp, 0, (size_t)n * sizeof(int));
    cudaMemsetAsync(is64p, 0, 4);
    cudaMemsetAsync(is64p, 1, 1);        // little-endian int 1
    k_detect<<<16, 256>>>((const unsigned int*)ei, 4096);
    k_hist<<<(E + 255) / 256, 256>>>(ei, E);
    k_scan1<<<nb, SCAN_BLK>>>(n);
    k_scan2<<<1, 1024>>>(nb);
    k_scan3<<<nb, SCAN_BLK>>>(n);
    k_scatter<<<(E + 255) / 256, 256>>>(ei, E);

    k_agg128<<<(n * 32 + 255) / 256, 256>>>(x, n);
    k_fused<<<(n + 127) / 128, 256, SMEM_BYTES>>>(agg1, x, Wl1, Wr1, b1,
                                                  Wl2, Wr2, pq, n);
    k_final<<<(n * 32 + 255) / 256, 256>>>(out, b2, n);
}